// round 1
// baseline (speedup 1.0000x reference)
#include <cuda_runtime.h>
#include <math.h>

#define Bq 2
#define Lq 1024
#define Aq 14
#define Kq 30
#define NRBF 16
#define EFq 128
#define EDGE_INq 3152
#define Mrows (Bq*Lq*Kq)   // 61440

// ---- scratch (__device__ globals; no allocations allowed) ----
__device__ int   g_Eidx[Mrows];
__device__ __align__(16) float g_X2[Bq*Lq*Aq*3];      // 86016 floats
__device__ __align__(16) float g_Wt[EDGE_INq*EFq];    // 403456 floats (transposed W)

// freq[m] = exp(-(2m)*ln(10000)/16) = 10^(-m/2)
__constant__ float c_freq[8] = {
    1.0f, 0.31622776601683794f, 0.1f, 0.031622776601683794f,
    0.01f, 0.0031622776601683794f, 0.001f, 0.00031622776601683794f
};

// =====================================================================
// Kernel 1: per-(b,i) masked CA distances + iterative top-K=30 selection
// (stable: ties break to the lower index, matching jax.lax.top_k)
// =====================================================================
__global__ void topk_kernel(const float* __restrict__ X,
                            const float* __restrict__ mask,
                            float* __restrict__ out_tail) {
    __shared__ float Da[Lq];
    __shared__ float svals[8];
    __shared__ int   sidx[8];
    __shared__ float sDmax;

    int bi  = blockIdx.x;          // 0..B*L-1
    int b   = bi >> 10;            // L = 1024
    int i   = bi & (Lq - 1);
    int tid = threadIdx.x;

    const float* Xb = X + (size_t)b * Lq * Aq * 3;
    float cx = Xb[(i*Aq+1)*3+0];
    float cy = Xb[(i*Aq+1)*3+1];
    float cz = Xb[(i*Aq+1)*3+2];
    float mi = mask[b*Lq + i];

    float lmax = 0.f;
    for (int j = tid; j < Lq; j += 256) {
        float dx = cx - Xb[(j*Aq+1)*3+0];
        float dy = cy - Xb[(j*Aq+1)*3+1];
        float dz = cz - Xb[(j*Aq+1)*3+2];
        float m2 = mi * mask[b*Lq + j];
        float D  = m2 * sqrtf(dx*dx + dy*dy + dz*dz + 1e-6f);
        Da[j] = D;
        lmax = fmaxf(lmax, D);
    }
    #pragma unroll
    for (int off = 16; off; off >>= 1)
        lmax = fmaxf(lmax, __shfl_xor_sync(0xffffffffu, lmax, off));
    if ((tid & 31) == 0) svals[tid >> 5] = lmax;
    __syncthreads();
    if (tid == 0) {
        float m = svals[0];
        for (int w = 1; w < 8; w++) m = fmaxf(m, svals[w]);
        sDmax = m;
    }
    __syncthreads();
    float Dmax = sDmax;
    for (int j = tid; j < Lq; j += 256) {
        float m2 = mi * mask[b*Lq + j];
        Da[j] += 2.f * (1.f - m2) * Dmax;
    }
    __syncthreads();

    for (int k = 0; k < Kq; k++) {
        float bv = 3.4e38f; int bj = 0x7fffffff;
        for (int j = tid; j < Lq; j += 256) {
            float v = Da[j];
            if (v < bv) { bv = v; bj = j; }     // ascending scan keeps lowest j on ties
        }
        #pragma unroll
        for (int off = 16; off; off >>= 1) {
            float ov = __shfl_down_sync(0xffffffffu, bv, off);
            int   oj = __shfl_down_sync(0xffffffffu, bj, off);
            if (ov < bv || (ov == bv && oj < bj)) { bv = ov; bj = oj; }
        }
        if ((tid & 31) == 0) { svals[tid >> 5] = bv; sidx[tid >> 5] = bj; }
        __syncthreads();
        if (tid == 0) {
            for (int w = 1; w < 8; w++) {
                float v = svals[w]; int jj = sidx[w];
                if (v < bv || (v == bv && jj < bj)) { bv = v; bj = jj; }
            }
            int orow = bi * Kq + k;
            g_Eidx[orow] = bj;
            if (out_tail) out_tail[orow] = (float)bj;
            Da[bj] = 3.4e38f;
        }
        __syncthreads();
    }
}

// =====================================================================
// Kernel 2: build X2 = [N, Ca, C, O, Cb, X[5:]]  (virtual Cb in slot 4)
// =====================================================================
__global__ void buildX2_kernel(const float* __restrict__ X) {
    int t = blockIdx.x * blockDim.x + threadIdx.x;
    if (t >= Bq * Lq) return;
    const float* xr = X + (size_t)t * Aq * 3;
    float* o = g_X2 + (size_t)t * Aq * 3;
    #pragma unroll
    for (int a = 0; a < Aq*3; a++) o[a] = xr[a];
    float Nx = xr[0],  Ny = xr[1],  Nz = xr[2];
    float Cax= xr[3],  Cay= xr[4],  Caz= xr[5];
    float Cx = xr[6],  Cy = xr[7],  Cz = xr[8];
    float bx = Cax - Nx, by = Cay - Ny, bz = Caz - Nz;
    float cx = Cx - Cax, cy = Cy - Cay, cz = Cz - Caz;
    float ax = by*cz - bz*cy;
    float ay = bz*cx - bx*cz;
    float az = bx*cy - by*cx;
    o[12] = -0.58273431f*ax + 0.56802827f*bx - 0.54067466f*cx + Cax;
    o[13] = -0.58273431f*ay + 0.56802827f*by - 0.54067466f*cy + Cay;
    o[14] = -0.58273431f*az + 0.56802827f*bz - 0.54067466f*cz + Caz;
}

// =====================================================================
// Kernel 3: transpose W (128 x 3152) -> Wt (3152 x 128) for coalesced B tiles
// =====================================================================
__global__ void transposeW_kernel(const float* __restrict__ W) {
    int t = blockIdx.x * blockDim.x + threadIdx.x;
    if (t < EFq * EDGE_INq) {
        int f = t / EDGE_INq;
        int c = t - f * EDGE_INq;
        g_Wt[c * EFq + f] = W[t];
    }
}

// =====================================================================
// Kernel 4: fused feature-gen + SGEMM (M=61440, N=128, Kdim=3152) + LayerNorm
// BM=64 rows, BN=128 (all cols), BK=16 (exactly one (p,q) atom pair per chunk)
// 256 threads: thread = (ty 0..7 -> 8 rows) x (lane 0..31 -> 4 cols)
// =====================================================================
#define SMEM_FLOATS 22848
#define SMEM_BYTES  (SMEM_FLOATS*4 + 128*4)   // + iidx/jidx ints = 91904 B

__global__ void __launch_bounds__(256, 2)
fused_gemm_kernel(const float* __restrict__ atom_mask,
                  const float* __restrict__ gamma_,
                  const float* __restrict__ beta_,
                  float* __restrict__ out) {
    extern __shared__ float sm[];
    float* xi   = sm;               // 64*42 = 2688
    float* xj   = sm + 2688;        // 2688
    float* ami  = sm + 5376;        // 64*14 = 896
    float* amj  = sm + 6272;        // 896
    float* Dsm  = sm + 7168;        // 196*64 = 12544, layout [pq][row]
    float* As   = sm + 19712;       // 16*64  = 1024,  layout [k][row]
    float* Bs   = sm + 20736;       // 16*128 = 2048,  layout [k][f]
    float* dpos = sm + 22784;       // 64
    int*   iidx = (int*)(sm + SMEM_FLOATS);   // 64
    int*   jidx = iidx + 64;                  // 64

    int tid  = threadIdx.x;
    int row0 = blockIdx.x << 6;     // 64 rows per block; 960 blocks exactly

    if (tid < 64) {
        int gr  = row0 + tid;
        int b   = gr / (Lq * Kq);
        int rem = gr - b * (Lq * Kq);
        int i   = rem / Kq;
        int j   = g_Eidx[gr];
        iidx[tid] = b * Lq + i;
        jidx[tid] = b * Lq + j;
        dpos[tid] = (float)(j - i);
    }
    __syncthreads();
    for (int e = tid; e < 64*42; e += 256) {
        int r = e / 42, c = e - r*42;
        xi[e] = g_X2[iidx[r]*42 + c];
        xj[e] = g_X2[jidx[r]*42 + c];
    }
    for (int e = tid; e < 64*14; e += 256) {
        int r = e / 14, c = e - r*14;
        ami[e] = 1.f - atom_mask[iidx[r]*14 + c];
        amj[e] = 1.f - atom_mask[jidx[r]*14 + c];
    }
    __syncthreads();
    // precompute all 196 atom-pair distances per row
    for (int e = tid; e < 196*64; e += 256) {
        int pq = e >> 6, r = e & 63;
        int p = pq / 14, q = pq - p*14;
        float dx = xi[r*42 + p*3+0] - xj[r*42 + q*3+0];
        float dy = xi[r*42 + p*3+1] - xj[r*42 + q*3+1];
        float dz = xi[r*42 + p*3+2] - xj[r*42 + q*3+2];
        Dsm[e] = sqrtf(dx*dx + dy*dy + dz*dz + 1e-6f);
    }

    int ty = tid >> 5, lane = tid & 31;
    float acc[8][4];
    #pragma unroll
    for (int u = 0; u < 8; u++) { acc[u][0]=0.f; acc[u][1]=0.f; acc[u][2]=0.f; acc[u][3]=0.f; }

    for (int ch = 0; ch < 197; ch++) {
        __syncthreads();                       // protect As/Bs reuse
        int c0 = ch << 4;
        // ---- load B tile (16 x 128) from transposed W, float4 coalesced ----
        #pragma unroll
        for (int u = 0; u < 2; u++) {
            int e4 = tid + u*256;              // 512 float4
            int kk = e4 >> 5;
            int f4 = e4 & 31;
            ((float4*)Bs)[e4] =
                ((const float4*)(g_Wt + (size_t)(c0 + kk) * EFq))[f4];
        }
        // ---- generate A tile (16 features x 64 rows) ----
        if (ch == 0) {
            // positional encoding: cos(d*freq[0..7]) then sin(d*freq[0..7])
            if (tid < 64) {
                float d = dpos[tid];
                #pragma unroll
                for (int m = 0; m < 8; m++) {
                    float s, c;
                    sincosf(d * c_freq[m], &s, &c);
                    As[m*64 + tid]     = c;
                    As[(m+8)*64 + tid] = s;
                }
            }
        } else {
            int pq = ch - 1;
            int p = pq / 14, q = pq - p*14;
            int r    = tid >> 4;               // rbf index 0..15
            int rowb = (tid & 15) << 2;        // 4 rows each
            float mu = (20.f/15.f) * (float)r;
            #pragma unroll
            for (int u = 0; u < 4; u++) {
                int row = rowb + u;
                float D  = Dsm[(pq << 6) + row];
                float co = ami[row*14 + p] * amj[row*14 + q];
                float x  = (D - mu) * 0.8f;    // 1/sigma, sigma = 1.25
                As[(r << 6) + row] = co * __expf(-x*x);
            }
        }
        __syncthreads();
        // ---- GEMM micro-tile: 8 rows x 4 cols per thread ----
        #pragma unroll
        for (int kk = 0; kk < 16; kk++) {
            float4 a0 = *(const float4*)&As[(kk << 6) + (ty << 3)];
            float4 a1 = *(const float4*)&As[(kk << 6) + (ty << 3) + 4];
            float4 bb = *(const float4*)&Bs[(kk << 7) + (lane << 2)];
            float av[8] = {a0.x, a0.y, a0.z, a0.w, a1.x, a1.y, a1.z, a1.w};
            float bw[4] = {bb.x, bb.y, bb.z, bb.w};
            #pragma unroll
            for (int u = 0; u < 8; u++)
                #pragma unroll
                for (int c = 0; c < 4; c++)
                    acc[u][c] += av[u] * bw[c];
        }
    }

    // ---- LayerNorm epilogue (warp owns full 128-col rows) ----
    float4 g4 = *(const float4*)&gamma_[lane << 2];
    float4 b4 = *(const float4*)&beta_[lane << 2];
    #pragma unroll
    for (int u = 0; u < 8; u++) {
        float s = acc[u][0] + acc[u][1] + acc[u][2] + acc[u][3];
        #pragma unroll
        for (int off = 16; off; off >>= 1) s += __shfl_xor_sync(0xffffffffu, s, off);
        float mean = s * (1.f/128.f);
        float d0 = acc[u][0]-mean, d1 = acc[u][1]-mean, d2 = acc[u][2]-mean, d3 = acc[u][3]-mean;
        float sq = d0*d0 + d1*d1 + d2*d2 + d3*d3;
        #pragma unroll
        for (int off = 16; off; off >>= 1) sq += __shfl_xor_sync(0xffffffffu, sq, off);
        float inv = rsqrtf(sq * (1.f/128.f) + 1e-5f);
        int gr = row0 + (ty << 3) + u;
        float4 o;
        o.x = d0*inv*g4.x + b4.x;
        o.y = d1*inv*g4.y + b4.y;
        o.z = d2*inv*g4.z + b4.z;
        o.w = d3*inv*g4.w + b4.w;
        *(float4*)&out[(size_t)gr * EFq + (lane << 2)] = o;
    }
}

// =====================================================================
extern "C" void kernel_launch(void* const* d_in, const int* in_sizes, int n_in,
                              void* d_out, int out_size) {
    const float* X         = (const float*)d_in[0];
    const float* mask      = (const float*)d_in[1];
    // d_in[2] residue_idx, d_in[3] chain_labels: unused by reference
    const float* atom_mask = (const float*)d_in[4];
    const float* W         = (const float*)d_in[5];
    const float* gamma_    = (const float*)d_in[6];
    const float* beta_     = (const float*)d_in[7];
    float* out = (float*)d_out;

    // tail = E_idx (as float) appended after E, if the harness allocated it
    float* out_tail = (out_size >= Mrows * (EFq + 1)) ? (out + (size_t)Mrows * EFq)
                                                      : nullptr;

    topk_kernel<<<Bq*Lq, 256>>>(X, mask, out_tail);
    buildX2_kernel<<<(Bq*Lq + 255)/256, 256>>>(X);
    transposeW_kernel<<<(EFq*EDGE_INq + 255)/256, 256>>>(W);

    cudaFuncSetAttribute(fused_gemm_kernel,
                         cudaFuncAttributeMaxDynamicSharedMemorySize, SMEM_BYTES);
    fused_gemm_kernel<<<Mrows/64, 256, SMEM_BYTES>>>(atom_mask, gamma_, beta_, out);
}